// round 12
// baseline (speedup 1.0000x reference)
#include <cuda_runtime.h>

#define NB 256
#define NT 256
#define HOIST_MAX 4096
#define FP_SCALE 1073741824.0f   // 2^30

__device__ unsigned long long g_sum[2];  // epoch-parity fixed-point accumulators
__device__ unsigned int g_tick;          // arrival ticket (monotonic, never reset)
__device__ unsigned int g_done;          // completion counter (monotonic, never reset)

__global__ void __launch_bounds__(NT, 2)
ril_fused_kernel(const float* __restrict__ x,
                 const float* __restrict__ weights,
                 const float* __restrict__ min_vals,
                 const float* __restrict__ max_vals,
                 const int* __restrict__ start_pos,
                 const int* __restrict__ offsets,
                 const int* __restrict__ sizes,
                 const int* __restrict__ out_mask,
                 float* __restrict__ out,
                 int B, int D, int G, int Wn, int OUTN, int total)
{
    // Shared: G floats (min_vals) | G int4 ({max,start,off,size}) | hoisted mask
    extern __shared__ float smv[];
    int4*  stab  = (int4*)(smv + G);
    float* smask = (float*)(stab + G);

    const int lane = threadIdx.x & 31;
    const int w    = threadIdx.x >> 5;
    const float inv_b = 1.0f / (float)B;

    // ---- Prefetch: x row-sum for this thread's first column (no shared dep) ----
    const int col0 = blockIdx.x * NT + threadIdx.x;
    float sx0 = 0.0f;
    if (col0 < D) {
        #pragma unroll 8
        for (int b = 0; b < B; ++b)
            sx0 += __ldg(x + (size_t)b * D + col0);
    }

    // ---- Preload tables (overlaps with x loads above) ----
    for (int i = threadIdx.x; i < G; i += NT) {
        smv[i] = __ldg(&min_vals[i]);
        int4 e;
        e.x = __float_as_int(__ldg(&max_vals[i]));
        e.y = __ldg(&start_pos[i]);
        e.z = __ldg(&offsets[i]);
        e.w = __ldg(&sizes[i]);
        stab[i] = e;
    }
    // Hoist this block's out_mask slice as 0/1 floats
    const int per = (total + (int)gridDim.x - 1) / (int)gridDim.x;
    const int j0  = blockIdx.x * per;
    const int j1  = min(j0 + per, total);
    const bool hoist = (per <= HOIST_MAX);
    if (hoist) {
        for (int j = j0 + threadIdx.x; j < j1; j += NT) {
            float m = 0.0f;
            if (j < OUTN) m = (__ldg(&out_mask[j]) != 0) ? 1.0f : 0.0f;
            smask[j - j0] = m;
        }
    }
    __syncthreads();

    const float m0 = smv[0];
    const float mL = smv[G - 1];
    const float inv_step = (mL > m0) ? (float)(G - 1) / (mL - m0) : 0.0f;

    // ---- Phase 1 ----
    float acc = 0.0f;
    const int stride = (int)gridDim.x * NT;
    for (int col = col0; col < D; col += stride) {
        float s;
        if (col == col0) {
            s = sx0;                       // prefetched
        } else {
            s = 0.0f;
            #pragma unroll 8
            for (int b = 0; b < B; ++b)
                s += __ldg(x + (size_t)b * D + col);
        }
        const float vv = s * inv_b;

        // searchsorted(min_vals, vv, 'right') - 1: interpolation + predicated fixup
        int g;
        if (!(vv >= m0)) {
            g = -1;
        } else {
            int gg = (int)floorf((vv - m0) * inv_step);
            gg = min(max(gg, 0), G - 1);
            gg -= (smv[gg] > vv) ? 1 : 0;
            gg -= (gg > 0 && smv[gg] > vv) ? 1 : 0;
            gg += (gg + 1 < G && smv[gg + 1] <= vv) ? 1 : 0;
            gg += (gg + 1 < G && smv[gg + 1] <= vv) ? 1 : 0;
            gg = max(gg, 0);
            bool ok = (smv[gg] <= vv) && (gg + 1 >= G || smv[gg + 1] > vv);
            if (!ok) {                     // general fallback
                int lo = 0, hi = G;
                while (lo < hi) {
                    int mid = (lo + hi) >> 1;
                    if (smv[mid] <= vv) lo = mid + 1; else hi = mid;
                }
                gg = lo - 1;
            }
            g = gg;
        }

        const int gc = min(max(g, 0), G - 1);
        const int4 e = stab[gc];
        const float mx = __int_as_float(e.x);
        bool in_range = (g >= 0) && (vv >= smv[gc]) && (vv <= mx);
        int pos = col - e.y;
        bool valid = in_range && (pos >= 0) && (pos < e.w);
        int widx = min(max(e.z + pos, 0), Wn - 1);
        float wv = valid ? __ldg(&weights[widx]) : 0.0f;
        acc += vv * wv;
    }

    // ---- Block reduce ----
    #pragma unroll
    for (int o = 16; o > 0; o >>= 1)
        acc += __shfl_down_sync(0xffffffffu, acc, o);
    __shared__ float red[NT / 32];
    if (lane == 0) red[w] = acc;
    __syncthreads();

    // ---- Global accumulate (deterministic fixed-point) + barrier ----
    __shared__ float s_val;
    if (threadIdx.x == 0) {
        float p = 0.0f;
        #pragma unroll
        for (int k = 0; k < NT / 32; ++k) p += red[k];

        const unsigned int nb = gridDim.x;
        unsigned int ticket = atomicAdd(&g_tick, 1u);
        unsigned int epoch  = ticket / nb;
        unsigned int slot   = epoch & 1u;

        long long q = llrintf(p * FP_SCALE);
        atomicAdd(&g_sum[slot], (unsigned long long)q);

        // release-add on done counter publishes the sum contribution
        asm volatile("red.release.gpu.global.add.u32 [%0], %1;"
                     :: "l"(&g_done), "r"(1u) : "memory");

        const unsigned int target = (epoch + 1u) * nb;
        unsigned int c;
        do {
            asm volatile("ld.acquire.gpu.u32 %0, [%1];" : "=r"(c) : "l"(&g_done));
        } while (c < target);

        // all contributions visible: read total
        unsigned long long raw = *(volatile unsigned long long*)&g_sum[slot];
        s_val = (float)((double)(long long)raw / (double)FP_SCALE);

        // first arrival of this epoch clears the other slot for the next replay
        if (ticket == epoch * nb)
            *(volatile unsigned long long*)&g_sum[slot ^ 1u] = 0ull;
    }
    __syncthreads();
    const float s = s_val;

    // ---- Output: masked broadcast from shared ----
    if (hoist) {
        for (int j = j0 + threadIdx.x; j < j1; j += NT)
            out[j] = s * smask[j - j0];
    } else {
        for (int j = j0 + threadIdx.x; j < j1; j += NT) {
            float o = 0.0f;
            if (j < OUTN) o = (__ldg(&out_mask[j]) != 0) ? s : 0.0f;
            out[j] = o;
        }
    }
}

extern "C" void kernel_launch(void* const* d_in, const int* in_sizes, int n_in,
                              void* d_out, int out_size)
{
    const float* x        = (const float*)d_in[0];
    const float* weights  = (const float*)d_in[1];
    const float* min_vals = (const float*)d_in[2];
    const float* max_vals = (const float*)d_in[3];
    const int*   start_p  = (const int*)d_in[4];
    const int*   offsets  = (const int*)d_in[5];
    const int*   sizes    = (const int*)d_in[6];
    const int*   out_mask = (const int*)d_in[7];
    float* out = (float*)d_out;

    int G  = in_sizes[2];
    int Wn = in_sizes[1];
    int D  = Wn / G;
    int B  = in_sizes[0] / D;
    int OUTN = in_sizes[7];

    int per = (out_size + NB - 1) / NB;
    int hoist_elems = (per <= HOIST_MAX) ? per : 0;
    size_t shmem = (size_t)G * (sizeof(float) + sizeof(int4))
                 + (size_t)hoist_elems * sizeof(float);

    ril_fused_kernel<<<NB, NT, shmem>>>(
        x, weights, min_vals, max_vals, start_p, offsets, sizes,
        out_mask, out, B, D, G, Wn, OUTN, out_size);
}